// round 13
// baseline (speedup 1.0000x reference)
#include <cuda_runtime.h>
#include <cuda.h>
#include <cuda_fp16.h>
#include <cstdint>

// ================= problem dims =================
#define P_DIM 2048
#define Q_DIM 2048
#define NBATCH 16
#define T_DIM 256
#define K_DATA 4096                 // (t,b) columns
#define K_EXTRA 4096                // start of boundary columns (16 of them)
#define K_COLS 4160                 // padded to 65 chunks of 64 (pad stays zero)

// ================= gemm config =================
#define TILE_M 128
#define TILE_N 128
#define CHUNK_K 64                  // halves per k-chunk = 128 bytes per row
#define NCHUNK (K_COLS / CHUNK_K)   // 65
#define NSTAGE 3
#define A_TILE_BYTES (TILE_M * 128) // 16384
#define B_TILE_BYTES (TILE_N * 128) // 16384
#define STAGE_BYTES (A_TILE_BYTES + B_TILE_BYTES)   // 32768
#define SMEM_DATA0 1024
#define SMEM_DYN_BYTES (SMEM_DATA0 + NSTAGE * STAGE_BYTES)  // 99328

// trace constants: exp(-0.001/0.02), exp(+0.001/0.02), exp(-0.001/0.101)
#define DECAY_PM 0.95122942450071400f
#define INV_PM   1.05127109637602410f
#define DECAY_X  0.99014786313283800f
#define A_TRIPLET 0.0065f

#define NTRACE_BLK 8192   // traces grid size == number of spike-count partials

// ============ static device scratch (no allocs; zero-initialized) ============
// pad cols [4112,4160) are NEVER written -> remain zero -> contribute 0 to GEMM
__device__ __half g_A[(size_t)P_DIM * K_COLS];  // [P,4160]: x_pre[t,b] | x_pre[T],b | 0-pad
__device__ __half g_B[(size_t)Q_DIM * K_COLS];  // [Q,4160]: fused B'   | bnd col    | 0-pad
__device__ unsigned int g_count_part[NTRACE_BLK];  // per-block spike counts (overwrite)

// ============ helpers ============
__device__ __forceinline__ uint32_t smem_u32(const void* p) {
    uint32_t a;
    asm("{ .reg .u64 t; cvta.to.shared.u64 t, %1; cvt.u32.u64 %0, t; }" : "=r"(a) : "l"(p));
    return a;
}
__device__ __forceinline__ uint32_t pack_h2(float lo, float hi) {
    __half2 h = __floats2half2_rn(lo, hi);
    return *reinterpret_cast<uint32_t*>(&h);
}

// Warp scan for linear recurrence x_{i+1} = a8*x_i + B_i. Returns the EXCLUSIVE
// prefix (trace value entering lane's segment); lane 0 gets 0.
__device__ __forceinline__ float warp_linrec_excl(float B, float a8, int lane) {
    float a = a8, b = B;
    #pragma unroll
    for (int o = 1; o < 32; o <<= 1) {
        float a_up = __shfl_up_sync(0xffffffffu, a, o);
        float b_up = __shfl_up_sync(0xffffffffu, b, o);
        if (lane >= o) {            // compose: x -> a*(a_up*x + b_up) + b
            b = fmaf(a, b_up, b);
            a = a * a_up;
        }
    }
    float x = __shfl_up_sync(0xffffffffu, b, 1);
    return (lane == 0) ? 0.f : x;
}

// ================= kernel 1: traces + fused operand packing (warp/sequence) =====
// One warp per (b, n) sequence; lane i owns t in [8i, 8i+8). Fully coalesced.
__global__ void __launch_bounds__(256) traces_kernel(
    const float* __restrict__ pre,
    const float* __restrict__ post,
    const float* __restrict__ apP,
    const float* __restrict__ amP)
{
    __shared__ unsigned s_cnt[8];
    int lane = threadIdx.x & 31;
    int wid = threadIdx.x >> 5;
    int w = blockIdx.x * 8 + wid;                // warp id 0..65535
    bool is_pre = w < (NBATCH * P_DIM);          // first 32768 warps: pre side
    int li = is_pre ? w : w - NBATCH * P_DIM;
    int n = li & (P_DIM - 1);
    int b = li >> 11;

    const float* src = (is_pre ? pre : post) + (((size_t)(b * P_DIM + n)) << 8) + lane * 8;
    float4 f0 = ((const float4*)src)[0];
    float4 f1 = ((const float4*)src)[1];
    float s[8] = {f0.x, f0.y, f0.z, f0.w, f1.x, f1.y, f1.z, f1.w};

    unsigned cnt = 0;
    #pragma unroll
    for (int j = 0; j < 8; j++) cnt += (s[j] > 0.5f) ? 1u : 0u;

    __half* o1 = (is_pre ? g_A : g_B) + (size_t)n * K_COLS + b * T_DIM + lane * 8;
    __half* ox = (is_pre ? g_A : g_B) + (size_t)n * K_COLS + K_EXTRA + b;

    float a2m = DECAY_PM * DECAY_PM, a4m = a2m * a2m, a8m = a4m * a4m;

    if (is_pre) {
        float B = 0.f;
        #pragma unroll
        for (int j = 0; j < 8; j++) B = DECAY_PM * (B + s[j]);
        float x = warp_linrec_excl(B, a8m, lane);
        float xa[8];
        #pragma unroll
        for (int j = 0; j < 8; j++) { xa[j] = x; x = DECAY_PM * (x + s[j]); }
        uint4 ua;
        ua.x = pack_h2(xa[0], xa[1]); ua.y = pack_h2(xa[2], xa[3]);
        ua.z = pack_h2(xa[4], xa[5]); ua.w = pack_h2(xa[6], xa[7]);
        *(uint4*)o1 = ua;
        if (lane == 31) *ox = __float2half(x);   // x_pre[T]
    } else {
        float Ap = *apP;
        float Am = *amP;
        float a2x = DECAY_X * DECAY_X, a4x = a2x * a2x, a8x = a4x * a4x;
        float Bm = 0.f, Bx = 0.f;
        #pragma unroll
        for (int j = 0; j < 8; j++) {
            Bm = DECAY_PM * (Bm + s[j]);
            Bx = DECAY_X * (Bx + s[j]);
        }
        float xm = warp_linrec_excl(Bm, a8m, lane);
        float xt = warp_linrec_excl(Bx, a8x, lane);
        float xmv[8];
        #pragma unroll
        for (int j = 0; j < 8; j++) { xmv[j] = xm; xm = DECAY_PM * (xm + s[j]); }
        float xmp = __shfl_up_sync(0xffffffffu, xmv[7], 1);   // prev segment's last xm
        if (lane == 0) xmp = 0.f;
        float v[8];
        #pragma unroll
        for (int j = 0; j < 8; j++) {
            v[j] = s[j] * (Ap + A_TRIPLET * xt) - Am * (xmp * INV_PM - xmv[j]);
            xmp = xmv[j];
            xt = DECAY_X * (xt + s[j]);
        }
        uint4 ua;
        ua.x = pack_h2(v[0], v[1]); ua.y = pack_h2(v[2], v[3]);
        ua.z = pack_h2(v[4], v[5]); ua.w = pack_h2(v[6], v[7]);
        *(uint4*)o1 = ua;
        if (lane == 31) *ox = __float2half(-Am * xmv[7] * INV_PM);   // -Am*x_post[T-1]/lam
    }

    // deterministic spike-count: warp reduce -> block reduce -> overwrite slot
    #pragma unroll
    for (int o = 16; o; o >>= 1) cnt += __shfl_xor_sync(0xffffffffu, cnt, o);
    if (lane == 0) s_cnt[wid] = cnt;
    __syncthreads();
    if (threadIdx.x == 0) {
        unsigned t = 0;
        #pragma unroll
        for (int i = 0; i < 8; i++) t += s_cnt[i];
        g_count_part[blockIdx.x] = t;
    }
}

// ================= mma.sync building blocks (sm_80-compatible PTX) =============
__device__ __forceinline__ void ldsm4(uint32_t& r0, uint32_t& r1, uint32_t& r2, uint32_t& r3,
                                      uint32_t addr) {
    asm volatile("ldmatrix.sync.aligned.m8n8.x4.shared.b16 {%0,%1,%2,%3}, [%4];"
                 : "=r"(r0), "=r"(r1), "=r"(r2), "=r"(r3) : "r"(addr));
}
__device__ __forceinline__ void mma16816(float* d, const uint32_t* a, uint32_t b0, uint32_t b1) {
    asm volatile(
        "mma.sync.aligned.m16n8k16.row.col.f32.f16.f16.f32 "
        "{%0,%1,%2,%3}, {%4,%5,%6,%7}, {%8,%9}, {%0,%1,%2,%3};"
        : "+f"(d[0]), "+f"(d[1]), "+f"(d[2]), "+f"(d[3])
        : "r"(a[0]), "r"(a[1]), "r"(a[2]), "r"(a[3]), "r"(b0), "r"(b1));
}
__device__ __forceinline__ void cpasync16(uint32_t dst, const void* src) {
    asm volatile("cp.async.cg.shared.global [%0], [%1], 16;" :: "r"(dst), "l"(src));
}

// ================= kernel 2: GEMM + fused epilogue =================
// grid (16,16) = 256 CTAs, 128 threads (warp grid 2x2, warp tile 64x64).
// MMA-first issue order: every kk starts with 32 register-ready HMMAs; the
// ldsm burst for kk+1, cp.async prefetch, and group waits all hide under them.
__global__ void __launch_bounds__(128) stdp_gemm_kernel(
    const float* __restrict__ weights,
    float* __restrict__ out)
{
    extern __shared__ __align__(1024) char smem[];
    uint32_t sb = smem_u32(smem);
    int tid = threadIdx.x;
    int wid = tid >> 5, lane = tid & 31;
    int m0 = blockIdx.x * TILE_M;
    int q0 = blockIdx.y * TILE_N;

    int wm = (wid & 1) * 64;        // warp M offset
    int wn = (wid >> 1) * 64;       // warp N offset
    const __half* Ag = g_A;
    const __half* Bg = g_B;

    float acc[128];
    #pragma unroll
    for (int i = 0; i < 128; i++) acc[i] = 0.f;

    // per-thread ldsm swizzled offsets; kch advance by XOR (kch0 in {0,1}, step 2k:
    // (kch0+2k)^r == (kch0^r)^2k since bit0 disjoint and no carry; addr ^= (2k<<4)).
    uint32_t a_off[4], b_off[4];
    {
        #pragma unroll
        for (int mt = 0; mt < 4; mt++) {
            int m_r = wm + mt * 16 + (lane & 15);
            int kch = lane >> 4;
            a_off[mt] = (uint32_t)(m_r * 128 + ((kch ^ (m_r & 7)) << 4));
        }
        int g = lane >> 3;
        #pragma unroll
        for (int pr = 0; pr < 4; pr++) {
            int n_r = wn + pr * 16 + (lane & 7) + (g >> 1) * 8;
            int kch = g & 1;
            b_off[pr] = (uint32_t)(n_r * 128 + ((kch ^ (n_r & 7)) << 4));
        }
    }

    // per-thread cp.async coords: 8 slices (i=0..7), each 1 A + 1 B 16B load.
    int ld_row = tid >> 3, ld_ch = tid & 7;   // rows 0..15 base; +16 per i
    uint32_t ld_so = (uint32_t)(ld_row * 128 + ((ld_ch ^ (ld_row & 7)) << 4));
    // row advances by 16 per i; row&7 invariant -> just add 16*128 bytes.

    #define PREF_SLICE(ii, a_d, b_d, kbase)                                           \
        do {                                                                          \
            uint32_t so = ld_so + (uint32_t)((ii) * 16 * 128);                        \
            cpasync16((a_d) + so,                                                     \
                      Ag + (size_t)(m0 + ld_row + (ii) * 16) * K_COLS + (kbase) + ld_ch * 8); \
            cpasync16((b_d) + so,                                                     \
                      Bg + (size_t)(q0 + ld_row + (ii) * 16) * K_COLS + (kbase) + ld_ch * 8); \
        } while (0)

    uint32_t af[2][4][4], bf[2][4][4];
    #define LOAD_FRAGS(fb, a_s, b_s, kk)                                          \
        do {                                                                      \
            uint32_t kx = (uint32_t)((kk) * 2) << 4;                              \
            _Pragma("unroll")                                                     \
            for (int mt = 0; mt < 4; mt++)                                        \
                ldsm4(af[fb][mt][0], af[fb][mt][1], af[fb][mt][2], af[fb][mt][3], \
                      (a_s) + (a_off[mt] ^ kx));                                  \
            _Pragma("unroll")                                                     \
            for (int pr = 0; pr < 4; pr++)                                        \
                ldsm4(bf[fb][pr][0], bf[fb][pr][1], bf[fb][pr][2], bf[fb][pr][3], \
                      (b_s) + (b_off[pr] ^ kx));                                  \
        } while (0)

    #define MMA_BLOCK(cb)                                                         \
        do {                                                                      \
            _Pragma("unroll")                                                     \
            for (int mt = 0; mt < 4; mt++) {                                      \
                _Pragma("unroll")                                                 \
                for (int nt = 0; nt < 8; nt++) {                                  \
                    int pr = nt >> 1, off = (nt & 1) * 2;                         \
                    mma16816(&acc[(mt * 8 + nt) * 4], af[cb][mt],                 \
                             bf[cb][pr][off], bf[cb][pr][off + 1]);               \
                }                                                                 \
            }                                                                     \
        } while (0)

    // ---- prologue: load chunks 0 and 1 ----
    {
        uint32_t a0 = sb + SMEM_DATA0, b0 = a0 + A_TILE_BYTES;
        uint32_t a1 = a0 + STAGE_BYTES, b1 = a1 + A_TILE_BYTES;
        #pragma unroll
        for (int i = 0; i < 8; i++) PREF_SLICE(i, a0, b0, 0);
        asm volatile("cp.async.commit_group;" ::: "memory");
        #pragma unroll
        for (int i = 0; i < 8; i++) PREF_SLICE(i, a1, b1, CHUNK_K);
        asm volatile("cp.async.commit_group;" ::: "memory");
    }
    asm volatile("cp.async.wait_group 1;" ::: "memory");   // chunk 0 resident
    __syncthreads();
    LOAD_FRAGS(0, sb + SMEM_DATA0, sb + SMEM_DATA0 + A_TILE_BYTES, 0);

    int s_cur = 0, s_nxt = 2;   // s_nxt = stage receiving chunk c+2
    #pragma unroll 1
    for (int c = 0; c < NCHUNK; c++) {
        // barrier: all warps done reading stage s_nxt (as chunk c-1) before rewrite
        __syncthreads();
        uint32_t a_s = sb + SMEM_DATA0 + s_cur * STAGE_BYTES;
        uint32_t b_s = a_s + A_TILE_BYTES;
        int s_n1 = (s_cur + 1 == NSTAGE) ? 0 : s_cur + 1;   // stage of chunk c+1
        uint32_t a_s1 = sb + SMEM_DATA0 + s_n1 * STAGE_BYTES;
        uint32_t b_s1 = a_s1 + A_TILE_BYTES;
        uint32_t an_s = sb + SMEM_DATA0 + s_nxt * STAGE_BYTES;
        uint32_t bn_s = an_s + A_TILE_BYTES;
        bool do_pref = (c + 2 < NCHUNK);
        int kbase2 = (c + 2) * CHUNK_K;

        // kk0: mma(buf0) first [frags preloaded pre-barrier], then kk1 frags + pref
        MMA_BLOCK(0);
        LOAD_FRAGS(1, a_s, b_s, 1);
        if (do_pref) { PREF_SLICE(0, an_s, bn_s, kbase2); PREF_SLICE(1, an_s, bn_s, kbase2); PREF_SLICE(2, an_s, bn_s, kbase2); }
        // kk1
        MMA_BLOCK(1);
        LOAD_FRAGS(0, a_s, b_s, 2);
        if (do_pref) { PREF_SLICE(3, an_s, bn_s, kbase2); PREF_SLICE(4, an_s, bn_s, kbase2); PREF_SLICE(5, an_s, bn_s, kbase2); }
        // kk2
        MMA_BLOCK(0);
        LOAD_FRAGS(1, a_s, b_s, 3);
        if (do_pref) {
            PREF_SLICE(6, an_s, bn_s, kbase2); PREF_SLICE(7, an_s, bn_s, kbase2);
            asm volatile("cp.async.commit_group;" ::: "memory");
        }
        // kk3: mma first (register-ready), then wait + preload next chunk's kk0
        MMA_BLOCK(1);
        if (do_pref) { asm volatile("cp.async.wait_group 1;" ::: "memory"); }
        else         { asm volatile("cp.async.wait_group 0;" ::: "memory"); }
        if (c + 1 < NCHUNK) LOAD_FRAGS(0, a_s1, b_s1, 0);

        s_cur = s_n1;
        s_nxt = (s_nxt + 1 == NSTAGE) ? 0 : s_nxt + 1;
    }
    #undef LOAD_FRAGS
    #undef MMA_BLOCK
    #undef PREF_SLICE

    // ---- spike-count reduction (8192 partials from traces_kernel) ----
    unsigned c2 = 0;
    {
        const uint4* cp4 = (const uint4*)g_count_part;
        #pragma unroll
        for (int i = 0; i < 16; i++) {
            uint4 vv = cp4[tid * 16 + i];
            c2 += vv.x + vv.y + vv.z + vv.w;
        }
    }
    #pragma unroll
    for (int o = 16; o; o >>= 1) c2 += __shfl_xor_sync(0xffffffffu, c2, o);
    unsigned* sc = (unsigned*)(smem + 128);   // header region, never a cp.async target
    if (lane == 0) sc[wid] = c2;
    __syncthreads();
    float act = (float)(sc[0] + sc[1] + sc[2] + sc[3]) * (1.0f / (NBATCH * T_DIM));
    float scale = sqrtf(0.1f / (act + 1e-6f));

    // ---- fused epilogue ----
    #pragma unroll
    for (int mt = 0; mt < 4; mt++) {
        int r0 = m0 + wm + mt * 16 + (lane >> 2);
        #pragma unroll
        for (int nt = 0; nt < 8; nt++) {
            int cidx = q0 + wn + nt * 8 + (lane & 3) * 2;
            const float* d = &acc[(mt * 8 + nt) * 4];
            {
                const float2 w = *(const float2*)(weights + (size_t)r0 * Q_DIM + cidx);
                float2 o;
                o.x = fminf(fmaxf(fmaf(d[0], scale, w.x), -2.f), 2.f);
                o.y = fminf(fmaxf(fmaf(d[1], scale, w.y), -2.f), 2.f);
                *(float2*)(out + (size_t)r0 * Q_DIM + cidx) = o;
            }
            {
                const float2 w = *(const float2*)(weights + (size_t)(r0 + 8) * Q_DIM + cidx);
                float2 o;
                o.x = fminf(fmaxf(fmaf(d[2], scale, w.x), -2.f), 2.f);
                o.y = fminf(fmaxf(fmaf(d[3], scale, w.y), -2.f), 2.f);
                *(float2*)(out + (size_t)(r0 + 8) * Q_DIM + cidx) = o;
            }
        }
    }
}

// ================= host =================
extern "C" void kernel_launch(void* const* d_in, const int* in_sizes, int n_in,
                              void* d_out, int out_size)
{
    const float* pre  = (const float*)d_in[0];
    const float* post = (const float*)d_in[1];
    const float* w    = (const float*)d_in[2];
    const float* ap   = (const float*)d_in[3];
    const float* am   = (const float*)d_in[4];
    float* out = (float*)d_out;

    traces_kernel<<<NTRACE_BLK, 256>>>(pre, post, ap, am);

    cudaFuncSetAttribute(stdp_gemm_kernel, cudaFuncAttributeMaxDynamicSharedMemorySize,
                         SMEM_DYN_BYTES);
    dim3 grid(P_DIM / TILE_M, Q_DIM / TILE_N);   // (16, 16)
    stdp_gemm_kernel<<<grid, 128, SMEM_DYN_BYTES>>>(w, out);
}

// round 14
// speedup vs baseline: 1.0467x; 1.0467x over previous
#include <cuda_runtime.h>
#include <cuda.h>
#include <cuda_fp16.h>
#include <cstdint>

// ================= problem dims =================
#define P_DIM 2048
#define Q_DIM 2048
#define NBATCH 16
#define T_DIM 256
#define K_DATA 4096                 // (t,b) columns
#define K_EXTRA 4096                // start of boundary columns (16 of them)
#define K_COLS 4160                 // padded to 65 chunks of 64 (pad stays zero)

// ================= gemm config =================
#define TILE_M 128
#define TILE_N 128
#define CHUNK_K 64                  // halves per k-chunk = 128 bytes per row
#define NCHUNK (K_COLS / CHUNK_K)   // 65
#define NSTAGE 3
#define A_TILE_BYTES (TILE_M * 128) // 16384
#define B_TILE_BYTES (TILE_N * 128) // 16384
#define STAGE_BYTES (A_TILE_BYTES + B_TILE_BYTES)   // 32768
#define SMEM_DATA0 1024
#define SMEM_DYN_BYTES (SMEM_DATA0 + NSTAGE * STAGE_BYTES)  // 99328

// trace constants: exp(-0.001/0.02), exp(+0.001/0.02), exp(-0.001/0.101)
#define DECAY_PM 0.95122942450071400f
#define INV_PM   1.05127109637602410f
#define DECAY_X  0.99014786313283800f
#define A_TRIPLET 0.0065f

#define NTRACE_BLK 4096   // traces grid size == number of spike-count partials

// ============ static device scratch (no allocs; zero-initialized) ============
// pad cols [4112,4160) are NEVER written -> remain zero -> contribute 0 to GEMM
__device__ __half g_A[(size_t)P_DIM * K_COLS];  // [P,4160]: x_pre[t,b] | x_pre[T],b | 0-pad
__device__ __half g_B[(size_t)Q_DIM * K_COLS];  // [Q,4160]: fused B'   | bnd col    | 0-pad
__device__ unsigned int g_count_part[NTRACE_BLK];  // per-block spike counts (overwrite)

// ============ helpers ============
__device__ __forceinline__ uint32_t smem_u32(const void* p) {
    uint32_t a;
    asm("{ .reg .u64 t; cvta.to.shared.u64 t, %1; cvt.u32.u64 %0, t; }" : "=r"(a) : "l"(p));
    return a;
}
__device__ __forceinline__ uint32_t pack_h2(float lo, float hi) {
    __half2 h = __floats2half2_rn(lo, hi);
    return *reinterpret_cast<uint32_t*>(&h);
}

// Warp scan for linear recurrence x_{i+1} = a8*x_i + B_i. Returns the EXCLUSIVE
// prefix (trace value entering lane's segment); lane 0 gets 0.
__device__ __forceinline__ float warp_linrec_excl(float B, float a8, int lane) {
    float a = a8, b = B;
    #pragma unroll
    for (int o = 1; o < 32; o <<= 1) {
        float a_up = __shfl_up_sync(0xffffffffu, a, o);
        float b_up = __shfl_up_sync(0xffffffffu, b, o);
        if (lane >= o) {            // compose: x -> a*(a_up*x + b_up) + b
            b = fmaf(a, b_up, b);
            a = a * a_up;
        }
    }
    float x = __shfl_up_sync(0xffffffffu, b, 1);
    return (lane == 0) ? 0.f : x;
}

// process one PRE sequence (8 spikes in s[]) -> writes trace row + boundary col
__device__ __forceinline__ unsigned trace_pre_seq(const float* s, __half* o1, __half* ox,
                                                  float a8m, int lane) {
    unsigned cnt = 0;
    #pragma unroll
    for (int j = 0; j < 8; j++) cnt += (s[j] > 0.5f) ? 1u : 0u;
    float B = 0.f;
    #pragma unroll
    for (int j = 0; j < 8; j++) B = DECAY_PM * (B + s[j]);
    float x = warp_linrec_excl(B, a8m, lane);
    float xa[8];
    #pragma unroll
    for (int j = 0; j < 8; j++) { xa[j] = x; x = DECAY_PM * (x + s[j]); }
    uint4 ua;
    ua.x = pack_h2(xa[0], xa[1]); ua.y = pack_h2(xa[2], xa[3]);
    ua.z = pack_h2(xa[4], xa[5]); ua.w = pack_h2(xa[6], xa[7]);
    *(uint4*)o1 = ua;
    if (lane == 31) *ox = __float2half(x);   // x_pre[T]
    return cnt;
}

// process one POST sequence -> fused B' row + boundary col
__device__ __forceinline__ unsigned trace_post_seq(const float* s, __half* o1, __half* ox,
                                                   float Ap, float Am,
                                                   float a8m, float a8x, int lane) {
    unsigned cnt = 0;
    #pragma unroll
    for (int j = 0; j < 8; j++) cnt += (s[j] > 0.5f) ? 1u : 0u;
    float Bm = 0.f, Bx = 0.f;
    #pragma unroll
    for (int j = 0; j < 8; j++) {
        Bm = DECAY_PM * (Bm + s[j]);
        Bx = DECAY_X * (Bx + s[j]);
    }
    float xm = warp_linrec_excl(Bm, a8m, lane);
    float xt = warp_linrec_excl(Bx, a8x, lane);
    float xmv[8];
    #pragma unroll
    for (int j = 0; j < 8; j++) { xmv[j] = xm; xm = DECAY_PM * (xm + s[j]); }
    float xmp = __shfl_up_sync(0xffffffffu, xmv[7], 1);   // prev segment's last xm
    if (lane == 0) xmp = 0.f;
    float v[8];
    #pragma unroll
    for (int j = 0; j < 8; j++) {
        v[j] = s[j] * (Ap + A_TRIPLET * xt) - Am * (xmp * INV_PM - xmv[j]);
        xmp = xmv[j];
        xt = DECAY_X * (xt + s[j]);
    }
    uint4 ua;
    ua.x = pack_h2(v[0], v[1]); ua.y = pack_h2(v[2], v[3]);
    ua.z = pack_h2(v[4], v[5]); ua.w = pack_h2(v[6], v[7]);
    *(uint4*)o1 = ua;
    if (lane == 31) *ox = __float2half(-Am * xmv[7] * INV_PM);   // -Am*x_post[T-1]/lam
    return cnt;
}

// ================= kernel 1: traces + fused operand packing ====================
// One warp per PAIR of consecutive sequences; the pair's source rows form one
// contiguous 2KB block, so all 4 LDG.128 issue before any scan math (seq1 load
// latency hides under seq0 scan). Pairs never straddle the pre/post boundary.
__global__ void __launch_bounds__(256) traces_kernel(
    const float* __restrict__ pre,
    const float* __restrict__ post,
    const float* __restrict__ apP,
    const float* __restrict__ amP)
{
    __shared__ unsigned s_cnt[8];
    int lane = threadIdx.x & 31;
    int wid = threadIdx.x >> 5;
    int wp = blockIdx.x * 8 + wid;               // warp-pair id 0..32767
    int s0 = wp * 2;                              // first sequence of the pair
    bool is_pre = s0 < (NBATCH * P_DIM);          // boundary (32768) is even
    int li0 = is_pre ? s0 : s0 - NBATCH * P_DIM;
    int n0 = li0 & (P_DIM - 1);
    int b0 = li0 >> 11;
    int li1 = li0 + 1;
    int n1 = li1 & (P_DIM - 1);
    int b1 = li1 >> 11;

    // flattened source index is linear: rows of the pair are contiguous
    const float* base = (is_pre ? pre : post) + (((size_t)li0) << 8) + lane * 8;
    float4 f00 = ((const float4*)base)[0];
    float4 f01 = ((const float4*)base)[1];
    float4 f10 = ((const float4*)(base + T_DIM))[0];
    float4 f11 = ((const float4*)(base + T_DIM))[1];
    float sA[8] = {f00.x, f00.y, f00.z, f00.w, f01.x, f01.y, f01.z, f01.w};
    float sB[8] = {f10.x, f10.y, f10.z, f10.w, f11.x, f11.y, f11.z, f11.w};

    __half* dst = is_pre ? g_A : g_B;
    __half* o1a = dst + (size_t)n0 * K_COLS + b0 * T_DIM + lane * 8;
    __half* oxa = dst + (size_t)n0 * K_COLS + K_EXTRA + b0;
    __half* o1b = dst + (size_t)n1 * K_COLS + b1 * T_DIM + lane * 8;
    __half* oxb = dst + (size_t)n1 * K_COLS + K_EXTRA + b1;

    float a2m = DECAY_PM * DECAY_PM, a4m = a2m * a2m, a8m = a4m * a4m;
    unsigned cnt;
    if (is_pre) {
        cnt  = trace_pre_seq(sA, o1a, oxa, a8m, lane);
        cnt += trace_pre_seq(sB, o1b, oxb, a8m, lane);
    } else {
        float Ap = *apP;
        float Am = *amP;
        float a2x = DECAY_X * DECAY_X, a4x = a2x * a2x, a8x = a4x * a4x;
        cnt  = trace_post_seq(sA, o1a, oxa, Ap, Am, a8m, a8x, lane);
        cnt += trace_post_seq(sB, o1b, oxb, Ap, Am, a8m, a8x, lane);
    }

    // deterministic spike-count: warp reduce -> block reduce -> overwrite slot
    #pragma unroll
    for (int o = 16; o; o >>= 1) cnt += __shfl_xor_sync(0xffffffffu, cnt, o);
    if (lane == 0) s_cnt[wid] = cnt;
    __syncthreads();
    if (threadIdx.x == 0) {
        unsigned t = 0;
        #pragma unroll
        for (int i = 0; i < 8; i++) t += s_cnt[i];
        g_count_part[blockIdx.x] = t;
    }
}

// ================= mma.sync building blocks (sm_80-compatible PTX) =============
__device__ __forceinline__ void ldsm4(uint32_t& r0, uint32_t& r1, uint32_t& r2, uint32_t& r3,
                                      uint32_t addr) {
    asm volatile("ldmatrix.sync.aligned.m8n8.x4.shared.b16 {%0,%1,%2,%3}, [%4];"
                 : "=r"(r0), "=r"(r1), "=r"(r2), "=r"(r3) : "r"(addr));
}
__device__ __forceinline__ void mma16816(float* d, const uint32_t* a, uint32_t b0, uint32_t b1) {
    asm volatile(
        "mma.sync.aligned.m16n8k16.row.col.f32.f16.f16.f32 "
        "{%0,%1,%2,%3}, {%4,%5,%6,%7}, {%8,%9}, {%0,%1,%2,%3};"
        : "+f"(d[0]), "+f"(d[1]), "+f"(d[2]), "+f"(d[3])
        : "r"(a[0]), "r"(a[1]), "r"(a[2]), "r"(a[3]), "r"(b0), "r"(b1));
}
__device__ __forceinline__ void cpasync16(uint32_t dst, const void* src) {
    asm volatile("cp.async.cg.shared.global [%0], [%1], 16;" :: "r"(dst), "l"(src));
}

// ================= kernel 2: GEMM + fused epilogue (R13 structure) =============
__global__ void __launch_bounds__(128) stdp_gemm_kernel(
    const float* __restrict__ weights,
    float* __restrict__ out)
{
    extern __shared__ __align__(1024) char smem[];
    uint32_t sb = smem_u32(smem);
    int tid = threadIdx.x;
    int wid = tid >> 5, lane = tid & 31;
    int m0 = blockIdx.x * TILE_M;
    int q0 = blockIdx.y * TILE_N;

    int wm = (wid & 1) * 64;        // warp M offset
    int wn = (wid >> 1) * 64;       // warp N offset
    const __half* Ag = g_A;
    const __half* Bg = g_B;

    float acc[128];
    #pragma unroll
    for (int i = 0; i < 128; i++) acc[i] = 0.f;

    // per-thread ldsm swizzled offsets; kch advance by XOR (kch0 in {0,1}, step 2k:
    // (kch0+2k)^r == (kch0^r)^2k since bit0 disjoint and no carry; addr ^= (2k<<4)).
    uint32_t a_off[4], b_off[4];
    {
        #pragma unroll
        for (int mt = 0; mt < 4; mt++) {
            int m_r = wm + mt * 16 + (lane & 15);
            int kch = lane >> 4;
            a_off[mt] = (uint32_t)(m_r * 128 + ((kch ^ (m_r & 7)) << 4));
        }
        int g = lane >> 3;
        #pragma unroll
        for (int pr = 0; pr < 4; pr++) {
            int n_r = wn + pr * 16 + (lane & 7) + (g >> 1) * 8;
            int kch = g & 1;
            b_off[pr] = (uint32_t)(n_r * 128 + ((kch ^ (n_r & 7)) << 4));
        }
    }

    // per-thread cp.async coords: 8 slices (i=0..7), each 1 A + 1 B 16B load.
    int ld_row = tid >> 3, ld_ch = tid & 7;   // rows 0..15 base; +16 per i
    uint32_t ld_so = (uint32_t)(ld_row * 128 + ((ld_ch ^ (ld_row & 7)) << 4));

    #define PREF_SLICE(ii, a_d, b_d, kbase)                                           \
        do {                                                                          \
            uint32_t so = ld_so + (uint32_t)((ii) * 16 * 128);                        \
            cpasync16((a_d) + so,                                                     \
                      Ag + (size_t)(m0 + ld_row + (ii) * 16) * K_COLS + (kbase) + ld_ch * 8); \
            cpasync16((b_d) + so,                                                     \
                      Bg + (size_t)(q0 + ld_row + (ii) * 16) * K_COLS + (kbase) + ld_ch * 8); \
        } while (0)

    uint32_t af[2][4][4], bf[2][4][4];
    #define LOAD_FRAGS(fb, a_s, b_s, kk)                                          \
        do {                                                                      \
            uint32_t kx = (uint32_t)((kk) * 2) << 4;                              \
            _Pragma("unroll")                                                     \
            for (int mt = 0; mt < 4; mt++)                                        \
                ldsm4(af[fb][mt][0], af[fb][mt][1], af[fb][mt][2], af[fb][mt][3], \
                      (a_s) + (a_off[mt] ^ kx));                                  \
            _Pragma("unroll")                                                     \
            for (int pr = 0; pr < 4; pr++)                                        \
                ldsm4(bf[fb][pr][0], bf[fb][pr][1], bf[fb][pr][2], bf[fb][pr][3], \
                      (b_s) + (b_off[pr] ^ kx));                                  \
        } while (0)

    #define MMA_BLOCK(cb)                                                         \
        do {                                                                      \
            _Pragma("unroll")                                                     \
            for (int mt = 0; mt < 4; mt++) {                                      \
                _Pragma("unroll")                                                 \
                for (int nt = 0; nt < 8; nt++) {                                  \
                    int pr = nt >> 1, off = (nt & 1) * 2;                         \
                    mma16816(&acc[(mt * 8 + nt) * 4], af[cb][mt],                 \
                             bf[cb][pr][off], bf[cb][pr][off + 1]);               \
                }                                                                 \
            }                                                                     \
        } while (0)

    // ---- prologue: load chunks 0 and 1 ----
    {
        uint32_t a0 = sb + SMEM_DATA0, b0 = a0 + A_TILE_BYTES;
        uint32_t a1 = a0 + STAGE_BYTES, b1 = a1 + A_TILE_BYTES;
        #pragma unroll
        for (int i = 0; i < 8; i++) PREF_SLICE(i, a0, b0, 0);
        asm volatile("cp.async.commit_group;" ::: "memory");
        #pragma unroll
        for (int i = 0; i < 8; i++) PREF_SLICE(i, a1, b1, CHUNK_K);
        asm volatile("cp.async.commit_group;" ::: "memory");
    }
    asm volatile("cp.async.wait_group 1;" ::: "memory");   // chunk 0 resident
    __syncthreads();
    LOAD_FRAGS(0, sb + SMEM_DATA0, sb + SMEM_DATA0 + A_TILE_BYTES, 0);

    int s_cur = 0, s_nxt = 2;   // s_nxt = stage receiving chunk c+2
    #pragma unroll 1
    for (int c = 0; c < NCHUNK; c++) {
        // barrier: all warps done reading stage s_nxt (as chunk c-1) before rewrite
        __syncthreads();
        uint32_t a_s = sb + SMEM_DATA0 + s_cur * STAGE_BYTES;
        uint32_t b_s = a_s + A_TILE_BYTES;
        int s_n1 = (s_cur + 1 == NSTAGE) ? 0 : s_cur + 1;   // stage of chunk c+1
        uint32_t a_s1 = sb + SMEM_DATA0 + s_n1 * STAGE_BYTES;
        uint32_t b_s1 = a_s1 + A_TILE_BYTES;
        uint32_t an_s = sb + SMEM_DATA0 + s_nxt * STAGE_BYTES;
        uint32_t bn_s = an_s + A_TILE_BYTES;
        bool do_pref = (c + 2 < NCHUNK);
        int kbase2 = (c + 2) * CHUNK_K;

        // kk0: mma(buf0) first [frags preloaded pre-barrier], then kk1 frags + pref
        MMA_BLOCK(0);
        LOAD_FRAGS(1, a_s, b_s, 1);
        if (do_pref) { PREF_SLICE(0, an_s, bn_s, kbase2); PREF_SLICE(1, an_s, bn_s, kbase2); PREF_SLICE(2, an_s, bn_s, kbase2); }
        // kk1
        MMA_BLOCK(1);
        LOAD_FRAGS(0, a_s, b_s, 2);
        if (do_pref) { PREF_SLICE(3, an_s, bn_s, kbase2); PREF_SLICE(4, an_s, bn_s, kbase2); PREF_SLICE(5, an_s, bn_s, kbase2); }
        // kk2
        MMA_BLOCK(0);
        LOAD_FRAGS(1, a_s, b_s, 3);
        if (do_pref) {
            PREF_SLICE(6, an_s, bn_s, kbase2); PREF_SLICE(7, an_s, bn_s, kbase2);
            asm volatile("cp.async.commit_group;" ::: "memory");
        }
        // kk3: mma first (register-ready), then wait + preload next chunk's kk0
        MMA_BLOCK(1);
        if (do_pref) { asm volatile("cp.async.wait_group 1;" ::: "memory"); }
        else         { asm volatile("cp.async.wait_group 0;" ::: "memory"); }
        if (c + 1 < NCHUNK) LOAD_FRAGS(0, a_s1, b_s1, 0);

        s_cur = s_n1;
        s_nxt = (s_nxt + 1 == NSTAGE) ? 0 : s_nxt + 1;
    }
    #undef LOAD_FRAGS
    #undef MMA_BLOCK
    #undef PREF_SLICE

    // ---- spike-count reduction (4096 partials from traces_kernel) ----
    unsigned c2 = 0;
    {
        const uint4* cp4 = (const uint4*)g_count_part;
        #pragma unroll
        for (int i = 0; i < 8; i++) {
            uint4 vv = cp4[tid * 8 + i];
            c2 += vv.x + vv.y + vv.z + vv.w;
        }
    }
    #pragma unroll
    for (int o = 16; o; o >>= 1) c2 += __shfl_xor_sync(0xffffffffu, c2, o);
    unsigned* sc = (unsigned*)(smem + 128);   // header region, never a cp.async target
    if (lane == 0) sc[wid] = c2;
    __syncthreads();
    float act = (float)(sc[0] + sc[1] + sc[2] + sc[3]) * (1.0f / (NBATCH * T_DIM));
    float scale = sqrtf(0.1f / (act + 1e-6f));

    // ---- fused epilogue ----
    #pragma unroll
    for (int mt = 0; mt < 4; mt++) {
        int r0 = m0 + wm + mt * 16 + (lane >> 2);
        #pragma unroll
        for (int nt = 0; nt < 8; nt++) {
            int cidx = q0 + wn + nt * 8 + (lane & 3) * 2;
            const float* d = &acc[(mt * 8 + nt) * 4];
            {
                const float2 w = *(const float2*)(weights + (size_t)r0 * Q_DIM + cidx);
                float2 o;
                o.x = fminf(fmaxf(fmaf(d[0], scale, w.x), -2.f), 2.f);
                o.y = fminf(fmaxf(fmaf(d[1], scale, w.y), -2.f), 2.f);
                *(float2*)(out + (size_t)r0 * Q_DIM + cidx) = o;
            }
            {
                const float2 w = *(const float2*)(weights + (size_t)(r0 + 8) * Q_DIM + cidx);
                float2 o;
                o.x = fminf(fmaxf(fmaf(d[2], scale, w.x), -2.f), 2.f);
                o.y = fminf(fmaxf(fmaf(d[3], scale, w.y), -2.f), 2.f);
                *(float2*)(out + (size_t)(r0 + 8) * Q_DIM + cidx) = o;
            }
        }
    }
}

// ================= host =================
extern "C" void kernel_launch(void* const* d_in, const int* in_sizes, int n_in,
                              void* d_out, int out_size)
{
    const float* pre  = (const float*)d_in[0];
    const float* post = (const float*)d_in[1];
    const float* w    = (const float*)d_in[2];
    const float* ap   = (const float*)d_in[3];
    const float* am   = (const float*)d_in[4];
    float* out = (float*)d_out;

    traces_kernel<<<NTRACE_BLK, 256>>>(pre, post, ap, am);

    cudaFuncSetAttribute(stdp_gemm_kernel, cudaFuncAttributeMaxDynamicSharedMemorySize,
                         SMEM_DYN_BYTES);
    dim3 grid(P_DIM / TILE_M, Q_DIM / TILE_N);   // (16, 16)
    stdp_gemm_kernel<<<grid, 128, SMEM_DYN_BYTES>>>(w, out);
}

// round 15
// speedup vs baseline: 1.0864x; 1.0380x over previous
#include <cuda_runtime.h>
#include <cuda.h>
#include <cuda_fp16.h>
#include <cstdint>

// ================= problem dims =================
#define P_DIM 2048
#define Q_DIM 2048
#define NBATCH 16
#define T_DIM 256
#define K_DATA 4096                 // (t,b) columns
#define K_EXTRA 4096                // start of boundary columns (16 of them)
#define K_COLS 4160                 // padded to 65 chunks of 64 (pad stays zero)

// ================= gemm config =================
#define TILE_M 128
#define TILE_N 256
#define CHUNK_K 64                  // halves per k-chunk = 128 bytes per row
#define NCHUNK (K_COLS / CHUNK_K)   // 65
#define NSTAGE 3
#define A_TILE_BYTES (TILE_M * 128) // 16384
#define B_TILE_BYTES (TILE_N * 128) // 32768
#define STAGE_BYTES (A_TILE_BYTES + B_TILE_BYTES)   // 49152
#define SMEM_DATA0 1024
#define SMEM_DYN_BYTES (SMEM_DATA0 + NSTAGE * STAGE_BYTES)  // 148480

// trace constants: exp(-0.001/0.02), exp(+0.001/0.02), exp(-0.001/0.101)
#define DECAY_PM 0.95122942450071400f
#define INV_PM   1.05127109637602410f
#define DECAY_X  0.99014786313283800f
#define A_TRIPLET 0.0065f

#define NTRACE_BLK 4096   // traces grid size == number of spike-count partials

// ============ static device scratch (no allocs; zero-initialized) ============
// pad cols [4112,4160) are NEVER written -> remain zero -> contribute 0 to GEMM
__device__ __half g_A[(size_t)P_DIM * K_COLS];  // [P,4160]: x_pre[t,b] | x_pre[T],b | 0-pad
__device__ __half g_B[(size_t)Q_DIM * K_COLS];  // [Q,4160]: fused B'   | bnd col    | 0-pad
__device__ unsigned int g_count_part[NTRACE_BLK];  // per-block spike counts (overwrite)

// ============ helpers ============
__device__ __forceinline__ uint32_t smem_u32(const void* p) {
    uint32_t a;
    asm("{ .reg .u64 t; cvta.to.shared.u64 t, %1; cvt.u32.u64 %0, t; }" : "=r"(a) : "l"(p));
    return a;
}
__device__ __forceinline__ uint32_t pack_h2(float lo, float hi) {
    __half2 h = __floats2half2_rn(lo, hi);
    return *reinterpret_cast<uint32_t*>(&h);
}

// Warp scan for linear recurrence x_{i+1} = a8*x_i + B_i. Returns the EXCLUSIVE
// prefix (trace value entering lane's segment); lane 0 gets 0.
__device__ __forceinline__ float warp_linrec_excl(float B, float a8, int lane) {
    float a = a8, b = B;
    #pragma unroll
    for (int o = 1; o < 32; o <<= 1) {
        float a_up = __shfl_up_sync(0xffffffffu, a, o);
        float b_up = __shfl_up_sync(0xffffffffu, b, o);
        if (lane >= o) {            // compose: x -> a*(a_up*x + b_up) + b
            b = fmaf(a, b_up, b);
            a = a * a_up;
        }
    }
    float x = __shfl_up_sync(0xffffffffu, b, 1);
    return (lane == 0) ? 0.f : x;
}

// process one PRE sequence (8 spikes in s[]) -> writes trace row + boundary col
__device__ __forceinline__ unsigned trace_pre_seq(const float* s, __half* o1, __half* ox,
                                                  float a8m, int lane) {
    unsigned cnt = 0;
    #pragma unroll
    for (int j = 0; j < 8; j++) cnt += (s[j] > 0.5f) ? 1u : 0u;
    float B = 0.f;
    #pragma unroll
    for (int j = 0; j < 8; j++) B = DECAY_PM * (B + s[j]);
    float x = warp_linrec_excl(B, a8m, lane);
    float xa[8];
    #pragma unroll
    for (int j = 0; j < 8; j++) { xa[j] = x; x = DECAY_PM * (x + s[j]); }
    uint4 ua;
    ua.x = pack_h2(xa[0], xa[1]); ua.y = pack_h2(xa[2], xa[3]);
    ua.z = pack_h2(xa[4], xa[5]); ua.w = pack_h2(xa[6], xa[7]);
    *(uint4*)o1 = ua;
    if (lane == 31) *ox = __float2half(x);   // x_pre[T]
    return cnt;
}

// process one POST sequence -> fused B' row + boundary col
__device__ __forceinline__ unsigned trace_post_seq(const float* s, __half* o1, __half* ox,
                                                   float Ap, float Am,
                                                   float a8m, float a8x, int lane) {
    unsigned cnt = 0;
    #pragma unroll
    for (int j = 0; j < 8; j++) cnt += (s[j] > 0.5f) ? 1u : 0u;
    float Bm = 0.f, Bx = 0.f;
    #pragma unroll
    for (int j = 0; j < 8; j++) {
        Bm = DECAY_PM * (Bm + s[j]);
        Bx = DECAY_X * (Bx + s[j]);
    }
    float xm = warp_linrec_excl(Bm, a8m, lane);
    float xt = warp_linrec_excl(Bx, a8x, lane);
    float xmv[8];
    #pragma unroll
    for (int j = 0; j < 8; j++) { xmv[j] = xm; xm = DECAY_PM * (xm + s[j]); }
    float xmp = __shfl_up_sync(0xffffffffu, xmv[7], 1);   // prev segment's last xm
    if (lane == 0) xmp = 0.f;
    float v[8];
    #pragma unroll
    for (int j = 0; j < 8; j++) {
        v[j] = s[j] * (Ap + A_TRIPLET * xt) - Am * (xmp * INV_PM - xmv[j]);
        xmp = xmv[j];
        xt = DECAY_X * (xt + s[j]);
    }
    uint4 ua;
    ua.x = pack_h2(v[0], v[1]); ua.y = pack_h2(v[2], v[3]);
    ua.z = pack_h2(v[4], v[5]); ua.w = pack_h2(v[6], v[7]);
    *(uint4*)o1 = ua;
    if (lane == 31) *ox = __float2half(-Am * xmv[7] * INV_PM);   // -Am*x_post[T-1]/lam
    return cnt;
}

// ================= kernel 1: traces (R14 structure, unchanged) ================
__global__ void __launch_bounds__(256) traces_kernel(
    const float* __restrict__ pre,
    const float* __restrict__ post,
    const float* __restrict__ apP,
    const float* __restrict__ amP)
{
    __shared__ unsigned s_cnt[8];
    int lane = threadIdx.x & 31;
    int wid = threadIdx.x >> 5;
    int wp = blockIdx.x * 8 + wid;               // warp-pair id 0..32767
    int s0 = wp * 2;                              // first sequence of the pair
    bool is_pre = s0 < (NBATCH * P_DIM);          // boundary (32768) is even
    int li0 = is_pre ? s0 : s0 - NBATCH * P_DIM;
    int n0 = li0 & (P_DIM - 1);
    int b0 = li0 >> 11;
    int li1 = li0 + 1;
    int n1 = li1 & (P_DIM - 1);
    int b1 = li1 >> 11;

    const float* base = (is_pre ? pre : post) + (((size_t)li0) << 8) + lane * 8;
    float4 f00 = ((const float4*)base)[0];
    float4 f01 = ((const float4*)base)[1];
    float4 f10 = ((const float4*)(base + T_DIM))[0];
    float4 f11 = ((const float4*)(base + T_DIM))[1];
    float sA[8] = {f00.x, f00.y, f00.z, f00.w, f01.x, f01.y, f01.z, f01.w};
    float sB[8] = {f10.x, f10.y, f10.z, f10.w, f11.x, f11.y, f11.z, f11.w};

    __half* dst = is_pre ? g_A : g_B;
    __half* o1a = dst + (size_t)n0 * K_COLS + b0 * T_DIM + lane * 8;
    __half* oxa = dst + (size_t)n0 * K_COLS + K_EXTRA + b0;
    __half* o1b = dst + (size_t)n1 * K_COLS + b1 * T_DIM + lane * 8;
    __half* oxb = dst + (size_t)n1 * K_COLS + K_EXTRA + b1;

    float a2m = DECAY_PM * DECAY_PM, a4m = a2m * a2m, a8m = a4m * a4m;
    unsigned cnt;
    if (is_pre) {
        cnt  = trace_pre_seq(sA, o1a, oxa, a8m, lane);
        cnt += trace_pre_seq(sB, o1b, oxb, a8m, lane);
    } else {
        float Ap = *apP;
        float Am = *amP;
        float a2x = DECAY_X * DECAY_X, a4x = a2x * a2x, a8x = a4x * a4x;
        cnt  = trace_post_seq(sA, o1a, oxa, Ap, Am, a8m, a8x, lane);
        cnt += trace_post_seq(sB, o1b, oxb, Ap, Am, a8m, a8x, lane);
    }

    #pragma unroll
    for (int o = 16; o; o >>= 1) cnt += __shfl_xor_sync(0xffffffffu, cnt, o);
    if (lane == 0) s_cnt[wid] = cnt;
    __syncthreads();
    if (threadIdx.x == 0) {
        unsigned t = 0;
        #pragma unroll
        for (int i = 0; i < 8; i++) t += s_cnt[i];
        g_count_part[blockIdx.x] = t;
    }
}

// ================= mma.sync building blocks (sm_80-compatible PTX) =============
__device__ __forceinline__ void ldsm4(uint32_t& r0, uint32_t& r1, uint32_t& r2, uint32_t& r3,
                                      uint32_t addr) {
    asm volatile("ldmatrix.sync.aligned.m8n8.x4.shared.b16 {%0,%1,%2,%3}, [%4];"
                 : "=r"(r0), "=r"(r1), "=r"(r2), "=r"(r3) : "r"(addr));
}
__device__ __forceinline__ void mma16816(float* d, const uint32_t* a, uint32_t b0, uint32_t b1) {
    asm volatile(
        "mma.sync.aligned.m16n8k16.row.col.f32.f16.f16.f32 "
        "{%0,%1,%2,%3}, {%4,%5,%6,%7}, {%8,%9}, {%0,%1,%2,%3};"
        : "+f"(d[0]), "+f"(d[1]), "+f"(d[2]), "+f"(d[3])
        : "r"(a[0]), "r"(a[1]), "r"(a[2]), "r"(a[3]), "r"(b0), "r"(b1));
}
__device__ __forceinline__ void cpasync16(uint32_t dst, const void* src) {
    asm volatile("cp.async.cg.shared.global [%0], [%1], 16;" :: "r"(dst), "l"(src));
}

// ================= kernel 2: GEMM + fused epilogue =================
// grid (16,8) = 128 CTAs, 256 threads (8 warps, warp grid 2x4, warp tile 64x64).
// 1 CTA/SM, one clean wave. Write-traffic dilution: smem demand 172 B/cyc vs
// 188 at 128x128 -> port cap rises 67% -> 74%.
__global__ void __launch_bounds__(256, 1) stdp_gemm_kernel(
    const float* __restrict__ weights,
    float* __restrict__ out)
{
    extern __shared__ __align__(1024) char smem[];
    uint32_t sb = smem_u32(smem);
    int tid = threadIdx.x;
    int wid = tid >> 5, lane = tid & 31;
    int m0 = blockIdx.x * TILE_M;
    int q0 = blockIdx.y * TILE_N;

    int wm = (wid & 1) * 64;        // warp M offset (2 groups)
    int wn = (wid >> 1) * 64;       // warp N offset (4 groups, 0..192)
    const __half* Ag = g_A;
    const __half* Bg = g_B;

    float acc[128];
    #pragma unroll
    for (int i = 0; i < 128; i++) acc[i] = 0.f;

    // per-thread ldsm swizzled offsets; kch advance by XOR (kch0 in {0,1}, step 2k:
    // (kch0+2k)^r == (kch0^r)^2k since bit0 disjoint and no carry; addr ^= (2k<<4)).
    uint32_t a_off[4], b_off[4];
    {
        #pragma unroll
        for (int mt = 0; mt < 4; mt++) {
            int m_r = wm + mt * 16 + (lane & 15);
            int kch = lane >> 4;
            a_off[mt] = (uint32_t)(m_r * 128 + ((kch ^ (m_r & 7)) << 4));
        }
        int g = lane >> 3;
        #pragma unroll
        for (int pr = 0; pr < 4; pr++) {
            int n_r = wn + pr * 16 + (lane & 7) + (g >> 1) * 8;
            int kch = g & 1;
            b_off[pr] = (uint32_t)(n_r * 128 + ((kch ^ (n_r & 7)) << 4));
        }
    }

    // per-thread cp.async coords: 12 slices/chunk (A: 4x32 rows, B: 8x32 rows).
    // 256 threads: ld_row = tid>>3 in 0..31, ld_ch = tid&7; rows +32 per slice.
    int ld_row = tid >> 3, ld_ch = tid & 7;
    uint32_t ld_so = (uint32_t)(ld_row * 128 + ((ld_ch ^ (ld_row & 7)) << 4));
    // row&7 invariant under +32 -> swizzle offset just adds 32*128 per slice.

    #define PREF_SLICE(ii, stage, kbase)                                              \
        do {                                                                          \
            if ((ii) < 4) {                                                           \
                uint32_t so = ld_so + (uint32_t)((ii) * 32 * 128);                    \
                cpasync16((stage) + so,                                               \
                    Ag + (size_t)(m0 + ld_row + (ii) * 32) * K_COLS + (kbase) + ld_ch * 8); \
            } else {                                                                  \
                uint32_t so = ld_so + (uint32_t)(((ii) - 4) * 32 * 128);              \
                cpasync16((stage) + A_TILE_BYTES + so,                                \
                    Bg + (size_t)(q0 + ld_row + ((ii) - 4) * 32) * K_COLS + (kbase) + ld_ch * 8); \
            }                                                                         \
        } while (0)

    uint32_t af[2][4][4], bf[2][4][4];
    #define LOAD_FRAGS(fb, a_s, b_s, kk)                                          \
        do {                                                                      \
            uint32_t kx = (uint32_t)((kk) * 2) << 4;                              \
            _Pragma("unroll")                                                     \
            for (int mt = 0; mt < 4; mt++)                                        \
                ldsm4(af[fb][mt][0], af[fb][mt][1], af[fb][mt][2], af[fb][mt][3], \
                      (a_s) + (a_off[mt] ^ kx));                                  \
            _Pragma("unroll")                                                     \
            for (int pr = 0; pr < 4; pr++)                                        \
                ldsm4(bf[fb][pr][0], bf[fb][pr][1], bf[fb][pr][2], bf[fb][pr][3], \
                      (b_s) + (b_off[pr] ^ kx));                                  \
        } while (0)

    #define MMA_BLOCK(cb)                                                         \
        do {                                                                      \
            _Pragma("unroll")                                                     \
            for (int mt = 0; mt < 4; mt++) {                                      \
                _Pragma("unroll")                                                 \
                for (int nt = 0; nt < 8; nt++) {                                  \
                    int pr = nt >> 1, off = (nt & 1) * 2;                         \
                    mma16816(&acc[(mt * 8 + nt) * 4], af[cb][mt],                 \
                             bf[cb][pr][off], bf[cb][pr][off + 1]);               \
                }                                                                 \
            }                                                                     \
        } while (0)

    // ---- prologue: load chunks 0 and 1 ----
    {
        uint32_t st0 = sb + SMEM_DATA0;
        uint32_t st1 = st0 + STAGE_BYTES;
        #pragma unroll
        for (int i = 0; i < 12; i++) PREF_SLICE(i, st0, 0);
        asm volatile("cp.async.commit_group;" ::: "memory");
        #pragma unroll
        for (int i = 0; i < 12; i++) PREF_SLICE(i, st1, CHUNK_K);
        asm volatile("cp.async.commit_group;" ::: "memory");
    }
    asm volatile("cp.async.wait_group 1;" ::: "memory");   // chunk 0 resident
    __syncthreads();
    LOAD_FRAGS(0, sb + SMEM_DATA0, sb + SMEM_DATA0 + A_TILE_BYTES, 0);

    int s_cur = 0, s_nxt = 2;   // s_nxt = stage receiving chunk c+2
    #pragma unroll 1
    for (int c = 0; c < NCHUNK; c++) {
        // barrier: all warps done reading stage s_nxt (as chunk c-1) before rewrite
        __syncthreads();
        uint32_t a_s = sb + SMEM_DATA0 + s_cur * STAGE_BYTES;
        uint32_t b_s = a_s + A_TILE_BYTES;
        int s_n1 = (s_cur + 1 == NSTAGE) ? 0 : s_cur + 1;   // stage of chunk c+1
        uint32_t a_s1 = sb + SMEM_DATA0 + s_n1 * STAGE_BYTES;
        uint32_t b_s1 = a_s1 + A_TILE_BYTES;
        uint32_t an_s = sb + SMEM_DATA0 + s_nxt * STAGE_BYTES;
        bool do_pref = (c + 2 < NCHUNK);
        int kbase2 = (c + 2) * CHUNK_K;

        // kk0: mma(buf0) first [frags preloaded pre-barrier], then kk1 frags + pref
        MMA_BLOCK(0);
        LOAD_FRAGS(1, a_s, b_s, 1);
        if (do_pref) { PREF_SLICE(0, an_s, kbase2); PREF_SLICE(1, an_s, kbase2);
                       PREF_SLICE(2, an_s, kbase2); PREF_SLICE(3, an_s, kbase2); }
        // kk1
        MMA_BLOCK(1);
        LOAD_FRAGS(0, a_s, b_s, 2);
        if (do_pref) { PREF_SLICE(4, an_s, kbase2); PREF_SLICE(5, an_s, kbase2);
                       PREF_SLICE(6, an_s, kbase2); PREF_SLICE(7, an_s, kbase2); }
        // kk2
        MMA_BLOCK(0);
        LOAD_FRAGS(1, a_s, b_s, 3);
        if (do_pref) {
            PREF_SLICE(8, an_s, kbase2); PREF_SLICE(9, an_s, kbase2);
            PREF_SLICE(10, an_s, kbase2); PREF_SLICE(11, an_s, kbase2);
            asm volatile("cp.async.commit_group;" ::: "memory");
        }
        // kk3: mma first (register-ready), then wait + preload next chunk's kk0
        MMA_BLOCK(1);
        if (do_pref) { asm volatile("cp.async.wait_group 1;" ::: "memory"); }
        else         { asm volatile("cp.async.wait_group 0;" ::: "memory"); }
        if (c + 1 < NCHUNK) LOAD_FRAGS(0, a_s1, b_s1, 0);

        s_cur = s_n1;
        s_nxt = (s_nxt + 1 == NSTAGE) ? 0 : s_nxt + 1;
    }
    #undef LOAD_FRAGS
    #undef MMA_BLOCK
    #undef PREF_SLICE

    // ---- spike-count reduction (4096 partials from traces_kernel) ----
    unsigned c2 = 0;
    {
        const uint4* cp4 = (const uint4*)g_count_part;
        #pragma unroll
        for (int i = 0; i < 4; i++) {
            uint4 vv = cp4[tid * 4 + i];
            c2 += vv.x + vv.y + vv.z + vv.w;
        }
    }
    #pragma unroll
    for (int o = 16; o; o >>= 1) c2 += __shfl_xor_sync(0xffffffffu, c2, o);
    unsigned* sc = (unsigned*)(smem + 128);   // header region, never a cp.async target
    if (lane == 0) sc[wid] = c2;
    __syncthreads();
    unsigned ct = 0;
    #pragma unroll
    for (int i = 0; i < 8; i++) ct += sc[i];
    float act = (float)ct * (1.0f / (NBATCH * T_DIM));
    float scale = sqrtf(0.1f / (act + 1e-6f));

    // ---- fused epilogue ----
    #pragma unroll
    for (int mt = 0; mt < 4; mt++) {
        int r0 = m0 + wm + mt * 16 + (lane >> 2);
        #pragma unroll
        for (int nt = 0; nt < 8; nt++) {
            int cidx = q0 + wn + nt * 8 + (lane & 3) * 2;
            const float* d = &acc[(mt * 8 + nt) * 4];
            {
                const float2 w = *(const float2*)(weights + (size_t)r0 * Q_DIM + cidx);
                float2 o;
                o.x = fminf(fmaxf(fmaf(d[0], scale, w.x), -2.f), 2.f);
                o.y = fminf(fmaxf(fmaf(d[1], scale, w.y), -2.f), 2.f);
                *(float2*)(out + (size_t)r0 * Q_DIM + cidx) = o;
            }
            {
                const float2 w = *(const float2*)(weights + (size_t)(r0 + 8) * Q_DIM + cidx);
                float2 o;
                o.x = fminf(fmaxf(fmaf(d[2], scale, w.x), -2.f), 2.f);
                o.y = fminf(fmaxf(fmaf(d[3], scale, w.y), -2.f), 2.f);
                *(float2*)(out + (size_t)(r0 + 8) * Q_DIM + cidx) = o;
            }
        }
    }
}

// ================= host =================
extern "C" void kernel_launch(void* const* d_in, const int* in_sizes, int n_in,
                              void* d_out, int out_size)
{
    const float* pre  = (const float*)d_in[0];
    const float* post = (const float*)d_in[1];
    const float* w    = (const float*)d_in[2];
    const float* ap   = (const float*)d_in[3];
    const float* am   = (const float*)d_in[4];
    float* out = (float*)d_out;

    traces_kernel<<<NTRACE_BLK, 256>>>(pre, post, ap, am);

    cudaFuncSetAttribute(stdp_gemm_kernel, cudaFuncAttributeMaxDynamicSharedMemorySize,
                         SMEM_DYN_BYTES);
    dim3 grid(P_DIM / TILE_M, Q_DIM / TILE_N);   // (16, 8)
    stdp_gemm_kernel<<<grid, 256, SMEM_DYN_BYTES>>>(w, out);
}